// round 7
// baseline (speedup 1.0000x reference)
#include <cuda_runtime.h>
#include <cstdint>

#define BATCH 4
#define SEQ   2048
#define NH    16
#define DH    64
#define DM    1024
#define QKVN  3072

// Scratch (device globals -- allocation-free per harness rules)
__device__ float g_q[(size_t)BATCH * NH * SEQ * DH];   // [b][h][s][dh] (tf32-rounded)
__device__ float g_k[(size_t)BATCH * NH * SEQ * DH];
__device__ float g_v[(size_t)BATCH * NH * SEQ * DH];
__device__ float g_ao[(size_t)BATCH * SEQ * DM];       // [b][s][d] attn out (tf32-rounded)
__device__ float g_xr[(size_t)BATCH * SEQ * DM];       // tf32-rounded x
__device__ float g_wr[(size_t)QKVN * DM];              // tf32-rounded W_qkv
__device__ float g_wor[(size_t)DM * DM];               // tf32-rounded W_o

// ---------------------------------------------------------------------------
// PTX helpers (portable: mma.sync + cp.async only)
// ---------------------------------------------------------------------------
__device__ __forceinline__ uint32_t smem_u32(const void* p) {
    uint32_t a;
    asm("{ .reg .u64 t; cvta.to.shared.u64 t, %1; cvt.u32.u64 %0, t; }" : "=r"(a) : "l"(p));
    return a;
}
__device__ __forceinline__ void cp_async16(uint32_t dst, const void* src) {
    asm volatile("cp.async.cg.shared.global [%0], [%1], 16;" :: "r"(dst), "l"(src) : "memory");
}
__device__ __forceinline__ void cp_commit() { asm volatile("cp.async.commit_group;" ::: "memory"); }
template <int N> __device__ __forceinline__ void cp_wait() {
    asm volatile("cp.async.wait_group %0;" :: "n"(N) : "memory");
}
__device__ __forceinline__ float rna_tf32(float x) {
    uint32_t u;
    asm("cvt.rna.tf32.f32 %0, %1;" : "=r"(u) : "f"(x));
    return __uint_as_float(u);
}
// D += A(16x8) * B(8x8), tf32 operands, fp32 accumulate
__device__ __forceinline__ void mma_tf32(float* d, const uint32_t* a, const uint32_t* b) {
    asm volatile(
        "mma.sync.aligned.m16n8k8.row.col.f32.tf32.tf32.f32 "
        "{%0,%1,%2,%3}, {%4,%5,%6,%7}, {%8,%9}, {%0,%1,%2,%3};"
        : "+f"(d[0]), "+f"(d[1]), "+f"(d[2]), "+f"(d[3])
        : "r"(a[0]), "r"(a[1]), "r"(a[2]), "r"(a[3]), "r"(b[0]), "r"(b[1]));
}

// ---------------------------------------------------------------------------
// Elementwise tf32 RNA round pass
// ---------------------------------------------------------------------------
__global__ void round_tf32_kernel(const float* __restrict__ src, float* __restrict__ dst, int n4)
{
    int i = blockIdx.x * blockDim.x + threadIdx.x;
    if (i < n4) {
        float4 v = ((const float4*)src)[i];
        v.x = rna_tf32(v.x); v.y = rna_tf32(v.y);
        v.z = rna_tf32(v.z); v.w = rna_tf32(v.w);
        ((float4*)dst)[i] = v;
    }
}

// ---------------------------------------------------------------------------
// TF32 mma.sync GEMM: C[M,N] = A[M,K] @ B[N,K]^T.  128x128 CTA tile, BK=32,
// 8 warps 2x4 -> 64x32 warp tile.  Double-buffered cp.async, ONE barrier per
// chunk: wait -> sync -> issue load(i+1) -> MMA(i).
// MODE 0: scatter C into g_q/g_k/g_v with rna-tf32 rounding.
// MODE 1: A = g_ao, write C row-major fp32 (final output).
// ---------------------------------------------------------------------------
#define TSTR   36
#define TILE_F (128 * TSTR)
#define GEMM_SMEM (4 * TILE_F * 4)

template <int MODE>
__global__ __launch_bounds__(256, 2) void gemm_mma(
    const float* __restrict__ A, const float* __restrict__ Bw,
    float* __restrict__ C, int M, int N, int K)
{
    extern __shared__ float smem[];
    float* Abuf[2] = { smem,          smem + 2 * TILE_F };
    float* Bbuf[2] = { smem + TILE_F, smem + 3 * TILE_F };
    uint32_t sbase = smem_u32(smem);

    const float* Ap = (MODE == 1) ? g_ao : A;

    int tid = threadIdx.x;
    int wid = tid >> 5, lane = tid & 31;
    int grp = lane >> 2, thr4 = lane & 3;
    int wm = wid >> 2, wn = wid & 3;
    int m0 = blockIdx.y << 7, n0 = blockIdx.x << 7;
    int nchunk = K >> 5;

    float acc[4][4][4];
#pragma unroll
    for (int mt = 0; mt < 4; mt++)
#pragma unroll
        for (int nt = 0; nt < 4; nt++)
#pragma unroll
            for (int e = 0; e < 4; e++) acc[mt][nt][e] = 0.f;

    auto load_chunk = [&](int chunk) {
        int buf = chunk & 1;
        uint32_t abase = sbase + (buf ? 2 * TILE_F : 0) * 4;
        uint32_t bbase = sbase + (buf ? 3 * TILE_F : 1 * TILE_F) * 4;
        int k0 = chunk << 5;
#pragma unroll
        for (int q = 0; q < 4; q++) {
            int idx = q * 256 + tid;
            int row = idx >> 3, c4 = idx & 7;
            uint32_t off = (uint32_t)(row * TSTR + c4 * 4) * 4;
            cp_async16(abase + off, Ap + (size_t)(m0 + row) * K + k0 + c4 * 4);
            cp_async16(bbase + off, Bw + (size_t)(n0 + row) * K + k0 + c4 * 4);
        }
        cp_commit();
    };

    load_chunk(0);

    for (int i = 0; i < nchunk; i++) {
        cp_wait<0>();          // this thread's load(i) done (only group outstanding)
        __syncthreads();       // everyone's load(i) done; everyone done MMA(i-1)
        if (i + 1 < nchunk) load_chunk(i + 1);   // buf used by i-1: safe now

        const uint32_t* Au = (const uint32_t*)Abuf[i & 1];
        const uint32_t* Bu = (const uint32_t*)Bbuf[i & 1];

#pragma unroll
        for (int ks = 0; ks < 4; ks++) {
            int ka = ks * 8 + thr4;
            uint32_t afr[4][4], bfr[4][2];
#pragma unroll
            for (int mt = 0; mt < 4; mt++) {
                int r0 = wm * 64 + mt * 16 + grp;
                afr[mt][0] = Au[r0 * TSTR + ka];
                afr[mt][1] = Au[(r0 + 8) * TSTR + ka];
                afr[mt][2] = Au[r0 * TSTR + ka + 4];
                afr[mt][3] = Au[(r0 + 8) * TSTR + ka + 4];
            }
#pragma unroll
            for (int nt = 0; nt < 4; nt++) {
                int rn = wn * 32 + nt * 8 + grp;
                bfr[nt][0] = Bu[rn * TSTR + ka];
                bfr[nt][1] = Bu[rn * TSTR + ka + 4];
            }
#pragma unroll
            for (int mt = 0; mt < 4; mt++)
#pragma unroll
                for (int nt = 0; nt < 4; nt++)
                    mma_tf32(acc[mt][nt], afr[mt], bfr[nt]);
        }
    }

#pragma unroll
    for (int mt = 0; mt < 4; mt++) {
#pragma unroll
        for (int nt = 0; nt < 4; nt++) {
            int m = m0 + wm * 64 + mt * 16 + grp;
            int n = n0 + wn * 32 + nt * 8 + 2 * thr4;
            if (MODE == 0) {
                float2 lo = make_float2(rna_tf32(acc[mt][nt][0]), rna_tf32(acc[mt][nt][1]));
                float2 hi = make_float2(rna_tf32(acc[mt][nt][2]), rna_tf32(acc[mt][nt][3]));
                int part = n >> 10;
                int d = n & 1023, h = d >> 6, dc = d & 63;
                float* dst = (part == 0) ? g_q : (part == 1) ? g_k : g_v;
                int b1 = m >> 11, s1 = m & 2047;
                *(float2*)(dst + ((((size_t)b1 * NH + h) * SEQ + s1) << 6) + dc) = lo;
                int s2 = (m + 8) & 2047;
                *(float2*)(dst + ((((size_t)b1 * NH + h) * SEQ + s2) << 6) + dc) = hi;
            } else {
                *(float2*)(C + (size_t)m * N + n) =
                    make_float2(acc[mt][nt][0], acc[mt][nt][1]);
                *(float2*)(C + (size_t)(m + 8) * N + n) =
                    make_float2(acc[mt][nt][2], acc[mt][nt][3]);
            }
        }
    }
}

// ---------------------------------------------------------------------------
// Tensor-core flash attention (tf32 mma.sync).
// Q-tile 128 x K-tile 64, 8 warps; warp w owns rows [16w,16w+16) -> softmax
// warp-local.  K/V double-buffered cp.async -> ONE barrier per KV tile, load
// of kt+1 overlaps compute of kt.  P never touches smem: the A-fragment for
// P@V is built by quad shuffles (holder lane = grp*4 + (t4>>1)(+2), parity
// t4&1).  Strides: Q/K 68, V 72 (conflict-free fragment reads).
// ---------------------------------------------------------------------------
#define QSTR 68
#define VSTR 72
// floats: Q 128*68 + 2*K 64*68 + 2*V 64*72 = 8704 + 8704 + 9216 = 26624
#define FM_SMEM (26624 * 4)

__global__ __launch_bounds__(256, 2) void flash_mma()
{
    extern __shared__ float sm[];
    float* Qs = sm;                              // [128][68]
    float* Kb[2] = { Qs + 128 * QSTR, Qs + 128 * QSTR + 64 * QSTR };
    float* Vb[2] = { Qs + 128 * QSTR + 2 * 64 * QSTR,
                     Qs + 128 * QSTR + 2 * 64 * QSTR + 64 * VSTR };

    int qt = blockIdx.x, bh = blockIdx.y;
    int b = bh >> 4, h = bh & 15;
    int tid = threadIdx.x, wid = tid >> 5, lane = tid & 31;
    int grp = lane >> 2, t4 = lane & 3;
    int qbase = lane & ~3;            // grp*4: first lane of this quad
    int half = t4 >> 1, par = t4 & 1;

    const float* Qg = g_q + ((size_t)bh * SEQ + (size_t)qt * 128) * DH;
    const float* Kg = g_k + (size_t)bh * SEQ * DH;
    const float* Vg = g_v + (size_t)bh * SEQ * DH;

    // Load Q tile: 128 rows x 64 cols = 2048 float4, 8 iters x 256 threads
#pragma unroll
    for (int u = 0; u < 8; u++) {
        int idx = u * 256 + tid;
        int r = idx >> 4, c4 = (idx & 15) << 2;
        *(float4*)&Qs[r * QSTR + c4] = *(const float4*)&Qg[r * DH + c4];
    }

    auto load_kv = [&](int kt, int buf) {
        uint32_t kbase = smem_u32(Kb[buf]);
        uint32_t vbase = smem_u32(Vb[buf]);
#pragma unroll
        for (int u = 0; u < 4; u++) {
            int idx = u * 256 + tid;
            int r = idx >> 4, c4 = (idx & 15) << 2;
            cp_async16(kbase + (uint32_t)(r * QSTR + c4) * 4,
                       Kg + ((size_t)kt * 64 + r) * DH + c4);
            cp_async16(vbase + (uint32_t)(r * VSTR + c4) * 4,
                       Vg + ((size_t)kt * 64 + r) * DH + c4);
        }
        cp_commit();
    };

    float accO[8][4];
#pragma unroll
    for (int nt = 0; nt < 8; nt++)
#pragma unroll
        for (int e = 0; e < 4; e++) accO[nt][e] = 0.f;
    float m0 = -1e30f, m1 = -1e30f, l0 = 0.f, l1 = 0.f;

    load_kv(0, 0);
    __syncthreads();   // Q visible to all warps

    int row0 = wid * 16 + grp;
    const uint32_t* Qu = (const uint32_t*)Qs;

    int nkt = 2 * qt + 2;
    for (int kt = 0; kt < nkt; kt++) {
        int buf = kt & 1;
        cp_wait<0>();          // this thread's KV(kt) done
        __syncthreads();       // all loads visible; all warps done PV(kt-1)
        if (kt + 1 < nkt) load_kv(kt + 1, buf ^ 1);

        const uint32_t* Ku = (const uint32_t*)Kb[buf];
        const uint32_t* Vu = (const uint32_t*)Vb[buf];

        // ---- S = Q @ K^T
        float s[8][4];
#pragma unroll
        for (int nt = 0; nt < 8; nt++)
#pragma unroll
            for (int e = 0; e < 4; e++) s[nt][e] = 0.f;

#pragma unroll
        for (int ks2 = 0; ks2 < 8; ks2++) {
            int ca = ks2 * 8 + t4;
            uint32_t a[4];
            a[0] = Qu[row0 * QSTR + ca];
            a[1] = Qu[(row0 + 8) * QSTR + ca];
            a[2] = Qu[row0 * QSTR + ca + 4];
            a[3] = Qu[(row0 + 8) * QSTR + ca + 4];
#pragma unroll
            for (int nt = 0; nt < 8; nt++) {
                uint32_t bf[2];
                bf[0] = Ku[(nt * 8 + grp) * QSTR + ca];
                bf[1] = Ku[(nt * 8 + grp) * QSTR + ca + 4];
                mma_tf32(s[nt], a, bf);
            }
        }

        // ---- scale + causal mask
#pragma unroll
        for (int nt = 0; nt < 8; nt++) {
            s[nt][0] *= 0.125f; s[nt][1] *= 0.125f;
            s[nt][2] *= 0.125f; s[nt][3] *= 0.125f;
        }
        if (kt >= 2 * qt) {
            int relk = (kt - 2 * qt) * 64;
#pragma unroll
            for (int nt = 0; nt < 8; nt++) {
                int k0 = relk + nt * 8 + 2 * t4;
                if (k0 > row0)         s[nt][0] = -1e30f;
                if (k0 + 1 > row0)     s[nt][1] = -1e30f;
                if (k0 > row0 + 8)     s[nt][2] = -1e30f;
                if (k0 + 1 > row0 + 8) s[nt][3] = -1e30f;
            }
        }

        // ---- online softmax (warp-local rows); s becomes rounded P
        float tm0 = -1e30f, tm1 = -1e30f;
#pragma unroll
        for (int nt = 0; nt < 8; nt++) {
            tm0 = fmaxf(tm0, fmaxf(s[nt][0], s[nt][1]));
            tm1 = fmaxf(tm1, fmaxf(s[nt][2], s[nt][3]));
        }
        tm0 = fmaxf(tm0, __shfl_xor_sync(0xffffffffu, tm0, 1));
        tm0 = fmaxf(tm0, __shfl_xor_sync(0xffffffffu, tm0, 2));
        tm1 = fmaxf(tm1, __shfl_xor_sync(0xffffffffu, tm1, 1));
        tm1 = fmaxf(tm1, __shfl_xor_sync(0xffffffffu, tm1, 2));
        float mn0 = fmaxf(m0, tm0), mn1 = fmaxf(m1, tm1);
        float al0 = __expf(m0 - mn0), al1 = __expf(m1 - mn1);
        float rs0 = 0.f, rs1 = 0.f;
#pragma unroll
        for (int nt = 0; nt < 8; nt++) {
            s[nt][0] = rna_tf32(__expf(s[nt][0] - mn0));
            s[nt][1] = rna_tf32(__expf(s[nt][1] - mn0));
            s[nt][2] = rna_tf32(__expf(s[nt][2] - mn1));
            s[nt][3] = rna_tf32(__expf(s[nt][3] - mn1));
            rs0 += s[nt][0] + s[nt][1];
            rs1 += s[nt][2] + s[nt][3];
        }
        rs0 += __shfl_xor_sync(0xffffffffu, rs0, 1);
        rs0 += __shfl_xor_sync(0xffffffffu, rs0, 2);
        rs1 += __shfl_xor_sync(0xffffffffu, rs1, 1);
        rs1 += __shfl_xor_sync(0xffffffffu, rs1, 2);
        l0 = l0 * al0 + rs0; l1 = l1 * al1 + rs1;
        m0 = mn0; m1 = mn1;
#pragma unroll
        for (int nt = 0; nt < 8; nt++) {
            accO[nt][0] *= al0; accO[nt][1] *= al0;
            accO[nt][2] *= al1; accO[nt][3] *= al1;
        }

        // ---- O += P @ V  (P A-fragments via quad shuffle transpose)
#pragma unroll
        for (int ks2 = 0; ks2 < 8; ks2++) {
            float e0 = __shfl_sync(0xffffffffu, s[ks2][0], qbase + half);
            float e1 = __shfl_sync(0xffffffffu, s[ks2][1], qbase + half);
            float e2 = __shfl_sync(0xffffffffu, s[ks2][2], qbase + half);
            float e3 = __shfl_sync(0xffffffffu, s[ks2][3], qbase + half);
            float f0 = __shfl_sync(0xffffffffu, s[ks2][0], qbase + half + 2);
            float f1 = __shfl_sync(0xffffffffu, s[ks2][1], qbase + half + 2);
            float f2 = __shfl_sync(0xffffffffu, s[ks2][2], qbase + half + 2);
            float f3 = __shfl_sync(0xffffffffu, s[ks2][3], qbase + half + 2);
            uint32_t a[4];
            a[0] = __float_as_uint(par ? e1 : e0);   // P[r0][ks2*8+t4]
            a[1] = __float_as_uint(par ? e3 : e2);   // P[r1][ks2*8+t4]
            a[2] = __float_as_uint(par ? f1 : f0);   // P[r0][ks2*8+t4+4]
            a[3] = __float_as_uint(par ? f3 : f2);   // P[r1][ks2*8+t4+4]
            int vr0 = (ks2 * 8 + t4) * VSTR + grp;
            int vr1 = (ks2 * 8 + t4 + 4) * VSTR + grp;
#pragma unroll
            for (int nt = 0; nt < 8; nt++) {
                uint32_t bf[2];
                bf[0] = Vu[vr0 + nt * 8];
                bf[1] = Vu[vr1 + nt * 8];
                mma_tf32(accO[nt], a, bf);
            }
        }
    }

    // ---- normalize + write (tf32-rounded, feeds tf32 O-proj)
    float inv0 = 1.f / l0, inv1 = 1.f / l1;
    int sq0 = qt * 128 + row0;
    float* O0 = g_ao + ((size_t)b * SEQ + sq0) * DM + h * DH;
    float* O1 = g_ao + ((size_t)b * SEQ + sq0 + 8) * DM + h * DH;
#pragma unroll
    for (int nt = 0; nt < 8; nt++) {
        int c = nt * 8 + 2 * t4;
        *(float2*)&O0[c] = make_float2(rna_tf32(accO[nt][0] * inv0),
                                       rna_tf32(accO[nt][1] * inv0));
        *(float2*)&O1[c] = make_float2(rna_tf32(accO[nt][2] * inv1),
                                       rna_tf32(accO[nt][3] * inv1));
    }
}

// ---------------------------------------------------------------------------
extern "C" void kernel_launch(void* const* d_in, const int* in_sizes, int n_in,
                              void* d_out, int out_size)
{
    const float* x    = (const float*)d_in[0];
    const float* Wqkv = (const float*)d_in[1];
    const float* Wo   = (const float*)d_in[2];
    float* out = (float*)d_out;

    cudaFuncSetAttribute(flash_mma,
                         cudaFuncAttributeMaxDynamicSharedMemorySize, FM_SMEM);
    cudaFuncSetAttribute(gemm_mma<0>,
                         cudaFuncAttributeMaxDynamicSharedMemorySize, GEMM_SMEM);
    cudaFuncSetAttribute(gemm_mma<1>,
                         cudaFuncAttributeMaxDynamicSharedMemorySize, GEMM_SMEM);

    int n4x = BATCH * SEQ * DM / 4;
    int n4w = QKVN * DM / 4;
    int n4o = DM * DM / 4;
    float* gx;  cudaGetSymbolAddress((void**)&gx,  g_xr);
    float* gw;  cudaGetSymbolAddress((void**)&gw,  g_wr);
    float* gwo; cudaGetSymbolAddress((void**)&gwo, g_wor);

    // 1) tf32-round GEMM inputs
    round_tf32_kernel<<<(n4x + 255) / 256, 256>>>(x, gx, n4x);
    round_tf32_kernel<<<(n4w + 255) / 256, 256>>>(Wqkv, gw, n4w);
    round_tf32_kernel<<<(n4o + 255) / 256, 256>>>(Wo, gwo, n4o);

    // 2) QKV projection (tf32 mma.sync)
    gemm_mma<0><<<dim3(QKVN / 128, (BATCH * SEQ) / 128), 256, GEMM_SMEM>>>(
        gx, gw, nullptr, BATCH * SEQ, QKVN, DM);

    // 3) Causal flash attention (tf32 mma.sync)
    flash_mma<<<dim3(SEQ / 128, BATCH * NH), 256, FM_SMEM>>>();

    // 4) Output projection (tf32 mma.sync)
    gemm_mma<1><<<dim3(DM / 128, (BATCH * SEQ) / 128), 256, GEMM_SMEM>>>(
        nullptr, gwo, out, BATCH * SEQ, DM, DM);
}

// round 8
// speedup vs baseline: 1.0250x; 1.0250x over previous
#include <cuda_runtime.h>
#include <cstdint>

#define BATCH 4
#define SEQ   2048
#define NH    16
#define DH    64
#define DM    1024
#define QKVN  3072

// Scratch (device globals -- allocation-free per harness rules)
__device__ float g_q[(size_t)BATCH * NH * SEQ * DH];   // [b][h][s][dh] (tf32-rounded)
__device__ float g_k[(size_t)BATCH * NH * SEQ * DH];
__device__ float g_v[(size_t)BATCH * NH * SEQ * DH];
__device__ float g_ao[(size_t)BATCH * SEQ * DM];       // [b][s][d] attn out (tf32-rounded)
__device__ float g_xr[(size_t)BATCH * SEQ * DM];       // tf32-rounded x
__device__ float g_wr[(size_t)QKVN * DM];              // tf32-rounded W_qkv
__device__ float g_wor[(size_t)DM * DM];               // tf32-rounded W_o

// ---------------------------------------------------------------------------
// PTX helpers (portable: mma.sync + cp.async + ldmatrix, no 'a'-features)
// ---------------------------------------------------------------------------
__device__ __forceinline__ uint32_t smem_u32(const void* p) {
    uint32_t a;
    asm("{ .reg .u64 t; cvta.to.shared.u64 t, %1; cvt.u32.u64 %0, t; }" : "=r"(a) : "l"(p));
    return a;
}
__device__ __forceinline__ void cp_async16(uint32_t dst, const void* src) {
    asm volatile("cp.async.cg.shared.global [%0], [%1], 16;" :: "r"(dst), "l"(src) : "memory");
}
__device__ __forceinline__ void cp_commit() { asm volatile("cp.async.commit_group;" ::: "memory"); }
template <int N> __device__ __forceinline__ void cp_wait() {
    asm volatile("cp.async.wait_group %0;" :: "n"(N) : "memory");
}
__device__ __forceinline__ float rna_tf32(float x) {
    uint32_t u;
    asm("cvt.rna.tf32.f32 %0, %1;" : "=r"(u) : "f"(x));
    return __uint_as_float(u);
}
// D += A(16x8) * B(8x8), tf32 operands, fp32 accumulate
__device__ __forceinline__ void mma_tf32(float* d, const uint32_t* a, const uint32_t* b) {
    asm volatile(
        "mma.sync.aligned.m16n8k8.row.col.f32.tf32.tf32.f32 "
        "{%0,%1,%2,%3}, {%4,%5,%6,%7}, {%8,%9}, {%0,%1,%2,%3};"
        : "+f"(d[0]), "+f"(d[1]), "+f"(d[2]), "+f"(d[3])
        : "r"(a[0]), "r"(a[1]), "r"(a[2]), "r"(a[3]), "r"(b[0]), "r"(b[1]));
}
// 16x8 fp32 tile = four 8x8 b16 matrices; x4 yields the tf32 A fragment.
__device__ __forceinline__ void ldsm_x4(uint32_t* r, uint32_t addr) {
    asm volatile("ldmatrix.sync.aligned.m8n8.x4.shared.b16 {%0,%1,%2,%3}, [%4];"
        : "=r"(r[0]), "=r"(r[1]), "=r"(r[2]), "=r"(r[3]) : "r"(addr));
}
// 8x8 fp32 tile = two 8x8 b16 matrices; x2 yields the tf32 B fragment.
__device__ __forceinline__ void ldsm_x2(uint32_t* r, uint32_t addr) {
    asm volatile("ldmatrix.sync.aligned.m8n8.x2.shared.b16 {%0,%1}, [%2];"
        : "=r"(r[0]), "=r"(r[1]) : "r"(addr));
}

// ---------------------------------------------------------------------------
// Elementwise tf32 RNA round pass
// ---------------------------------------------------------------------------
__global__ void round_tf32_kernel(const float* __restrict__ src, float* __restrict__ dst, int n4)
{
    int i = blockIdx.x * blockDim.x + threadIdx.x;
    if (i < n4) {
        float4 v = ((const float4*)src)[i];
        v.x = rna_tf32(v.x); v.y = rna_tf32(v.y);
        v.z = rna_tf32(v.z); v.w = rna_tf32(v.w);
        ((float4*)dst)[i] = v;
    }
}

// ---------------------------------------------------------------------------
// TF32 mma.sync GEMM: C[M,N] = A[M,K] @ B[N,K]^T.  128x128 CTA tile, BK=32,
// 8 warps 2x4 -> 64x32 warp tile.  Double-buffered smem (cp.async) AND
// double-buffered register fragments (ldmatrix) -> MMAs of ks overlap the
// fragment loads of ks+1; tensor pipe stays fed.
// MODE 0: scatter C into g_q/g_k/g_v with rna-tf32 rounding.
// MODE 1: A = g_ao, write C row-major fp32 (final output).
// ---------------------------------------------------------------------------
#define TSTR   36
#define TILE_F (128 * TSTR)
#define GEMM_SMEM (4 * TILE_F * 4)

template <int MODE>
__global__ __launch_bounds__(256) void gemm_mma(
    const float* __restrict__ A, const float* __restrict__ Bw,
    float* __restrict__ C, int M, int N, int K)
{
    extern __shared__ float smem[];
    uint32_t sbase = smem_u32(smem);

    const float* Ap = (MODE == 1) ? g_ao : A;

    int tid = threadIdx.x;
    int wid = tid >> 5, lane = tid & 31;
    int grp = lane >> 2, thr4 = lane & 3;
    int wm = wid >> 2, wn = wid & 3;
    int m0 = blockIdx.y << 7, n0 = blockIdx.x << 7;
    int nchunk = K >> 5;

    // ldmatrix per-lane byte offsets (within a tile buffer)
    uint32_t a_off = (uint32_t)(((wm * 64 + (lane & 7) + ((lane >> 3) & 1) * 8) * TSTR
                                + ((lane >> 4) * 4)) * 4);
    uint32_t b_off = (uint32_t)(((wn * 32 + (lane & 7)) * TSTR
                                + (((lane >> 3) & 1) * 4)) * 4);

    float acc[4][4][4];
#pragma unroll
    for (int mt = 0; mt < 4; mt++)
#pragma unroll
        for (int nt = 0; nt < 4; nt++)
#pragma unroll
            for (int e = 0; e < 4; e++) acc[mt][nt][e] = 0.f;

    auto load_chunk = [&](int chunk) {
        int buf = chunk & 1;
        uint32_t abase = sbase + (buf ? 2 * TILE_F : 0) * 4;
        uint32_t bbase = sbase + (buf ? 3 * TILE_F : 1 * TILE_F) * 4;
        int k0 = chunk << 5;
#pragma unroll
        for (int q = 0; q < 4; q++) {
            int idx = q * 256 + tid;
            int row = idx >> 3, c4 = idx & 7;
            uint32_t off = (uint32_t)(row * TSTR + c4 * 4) * 4;
            cp_async16(abase + off, Ap + (size_t)(m0 + row) * K + k0 + c4 * 4);
            cp_async16(bbase + off, Bw + (size_t)(n0 + row) * K + k0 + c4 * 4);
        }
        cp_commit();
    };

    uint32_t afr[2][4][4], bfr[2][4][2];
    auto frag_load = [&](int ks, uint32_t abuf, uint32_t bbuf, int fb) {
#pragma unroll
        for (int mt = 0; mt < 4; mt++)
            ldsm_x4(afr[fb][mt], abuf + a_off + mt * (16 * TSTR * 4) + ks * 32);
#pragma unroll
        for (int nt = 0; nt < 4; nt++)
            ldsm_x2(bfr[fb][nt], bbuf + b_off + nt * (8 * TSTR * 4) + ks * 32);
    };

    load_chunk(0);
    cp_wait<0>();
    __syncthreads();
    frag_load(0, sbase, sbase + TILE_F * 4, 0);

    for (int i = 0; i < nchunk; i++) {
        int buf = i & 1;
        uint32_t abuf = sbase + (buf ? 2 * TILE_F : 0) * 4;
        uint32_t bbuf = sbase + (buf ? 3 * TILE_F : 1 * TILE_F) * 4;
        if (i + 1 < nchunk) load_chunk(i + 1);   // all warps past prev sync

#pragma unroll
        for (int ks = 0; ks < 4; ks++) {
            int pf = ks & 1;
            if (ks < 3) frag_load(ks + 1, abuf, bbuf, pf ^ 1);
#pragma unroll
            for (int mt = 0; mt < 4; mt++)
#pragma unroll
                for (int nt = 0; nt < 4; nt++)
                    mma_tf32(acc[mt][nt], afr[pf][mt], bfr[pf][nt]);
        }

        if (i + 1 < nchunk) {
            cp_wait<0>();
            __syncthreads();
            int nb = (i + 1) & 1;
            frag_load(0, sbase + (nb ? 2 * TILE_F : 0) * 4,
                         sbase + (nb ? 3 * TILE_F : 1 * TILE_F) * 4, 0);
        }
    }

#pragma unroll
    for (int mt = 0; mt < 4; mt++) {
#pragma unroll
        for (int nt = 0; nt < 4; nt++) {
            int m = m0 + wm * 64 + mt * 16 + grp;
            int n = n0 + wn * 32 + nt * 8 + 2 * thr4;
            if (MODE == 0) {
                float2 lo = make_float2(rna_tf32(acc[mt][nt][0]), rna_tf32(acc[mt][nt][1]));
                float2 hi = make_float2(rna_tf32(acc[mt][nt][2]), rna_tf32(acc[mt][nt][3]));
                int part = n >> 10;
                int d = n & 1023, h = d >> 6, dc = d & 63;
                float* dst = (part == 0) ? g_q : (part == 1) ? g_k : g_v;
                int b1 = m >> 11, s1 = m & 2047;
                *(float2*)(dst + ((((size_t)b1 * NH + h) * SEQ + s1) << 6) + dc) = lo;
                int s2 = (m + 8) & 2047;
                *(float2*)(dst + ((((size_t)b1 * NH + h) * SEQ + s2) << 6) + dc) = hi;
            } else {
                *(float2*)(C + (size_t)m * N + n) =
                    make_float2(acc[mt][nt][0], acc[mt][nt][1]);
                *(float2*)(C + (size_t)(m + 8) * N + n) =
                    make_float2(acc[mt][nt][2], acc[mt][nt][3]);
            }
        }
    }
}

// ---------------------------------------------------------------------------
// Tensor-core flash attention (tf32 mma.sync).
// Q-tile 128 x K-tile 64, 8 warps; warp w owns rows [16w,16w+16) -> softmax
// warp-local.  KV double-buffered cp.async (load kt+1 overlaps compute kt,
// one barrier/iter).  Q fragments hoisted into registers once (ldmatrix);
// K and P fragments via ldmatrix; P through warp-private smem (+syncwarp);
// V via scalar LDS (k-major layout, stride 72 -> conflict-free).
// ---------------------------------------------------------------------------
#define QSTR 68
#define VSTR 72
// floats: Q 128*68 + 2*K 64*68 + 2*V 64*72 + P 128*68 = 35328
#define FM_SMEM (35328 * 4)

__global__ __launch_bounds__(256) void flash_mma()
{
    extern __shared__ float sm[];
    float* Qs = sm;                                       // [128][68]
    float* Kb[2] = { Qs + 128 * QSTR, Qs + 128 * QSTR + 64 * QSTR };
    float* Vb[2] = { Qs + 128 * QSTR + 2 * 64 * QSTR,
                     Qs + 128 * QSTR + 2 * 64 * QSTR + 64 * VSTR };
    float* Ps = Qs + 128 * QSTR + 2 * 64 * QSTR + 2 * 64 * VSTR;  // [128][68]

    int qt = blockIdx.x, bh = blockIdx.y;
    int b = bh >> 4, h = bh & 15;
    int tid = threadIdx.x, wid = tid >> 5, lane = tid & 31;
    int grp = lane >> 2, t4 = lane & 3;

    const float* Qg = g_q + ((size_t)bh * SEQ + (size_t)qt * 128) * DH;
    const float* Kg = g_k + (size_t)bh * SEQ * DH;
    const float* Vg = g_v + (size_t)bh * SEQ * DH;

    // ldmatrix per-lane offsets
    uint32_t qp_off = (uint32_t)(((wid * 16 + (lane & 7) + ((lane >> 3) & 1) * 8) * QSTR
                                 + ((lane >> 4) * 4)) * 4);          // Q and P (A frags)
    uint32_t k_off  = (uint32_t)((((lane & 7)) * QSTR
                                 + (((lane >> 3) & 1) * 4)) * 4);    // K (B frags)
    uint32_t qs_base = smem_u32(Qs);
    uint32_t ps_base = smem_u32(Ps);

    // Load Q tile: 128 rows x 64 cols = 2048 float4
#pragma unroll
    for (int u = 0; u < 8; u++) {
        int idx = u * 256 + tid;
        int r = idx >> 4, c4 = (idx & 15) << 2;
        *(float4*)&Qs[r * QSTR + c4] = *(const float4*)&Qg[r * DH + c4];
    }

    auto load_kv = [&](int kt, int buf) {
        uint32_t kbase = smem_u32(Kb[buf]);
        uint32_t vbase = smem_u32(Vb[buf]);
#pragma unroll
        for (int u = 0; u < 4; u++) {
            int idx = u * 256 + tid;
            int r = idx >> 4, c4 = (idx & 15) << 2;
            cp_async16(kbase + (uint32_t)(r * QSTR + c4) * 4,
                       Kg + ((size_t)kt * 64 + r) * DH + c4);
            cp_async16(vbase + (uint32_t)(r * VSTR + c4) * 4,
                       Vg + ((size_t)kt * 64 + r) * DH + c4);
        }
        cp_commit();
    };

    float accO[8][4];
#pragma unroll
    for (int nt = 0; nt < 8; nt++)
#pragma unroll
        for (int e = 0; e < 4; e++) accO[nt][e] = 0.f;
    float m0 = -1e30f, m1 = -1e30f, l0 = 0.f, l1 = 0.f;

    load_kv(0, 0);
    __syncthreads();   // Q visible

    // Hoist Q fragments for the whole kernel (8 k-steps x 4 regs)
    uint32_t qf[8][4];
#pragma unroll
    for (int ks2 = 0; ks2 < 8; ks2++)
        ldsm_x4(qf[ks2], qs_base + qp_off + ks2 * 32);

    int row0 = wid * 16 + grp;

    int nkt = 2 * qt + 2;
    for (int kt = 0; kt < nkt; kt++) {
        int buf = kt & 1;
        cp_wait<0>();
        __syncthreads();   // KV(kt) visible; all warps done PV(kt-1)
        if (kt + 1 < nkt) load_kv(kt + 1, buf ^ 1);

        uint32_t kbase = smem_u32(Kb[buf]);
        const uint32_t* Vu = (const uint32_t*)Vb[buf];

        // ---- S = Q @ K^T  (K B-frags via ldmatrix)
        float s[8][4];
#pragma unroll
        for (int nt = 0; nt < 8; nt++)
#pragma unroll
            for (int e = 0; e < 4; e++) s[nt][e] = 0.f;

#pragma unroll
        for (int ks2 = 0; ks2 < 8; ks2++) {
            uint32_t kf[8][2];
#pragma unroll
            for (int nt = 0; nt < 8; nt++)
                ldsm_x2(kf[nt], kbase + k_off + nt * (8 * QSTR * 4) + ks2 * 32);
#pragma unroll
            for (int nt = 0; nt < 8; nt++)
                mma_tf32(s[nt], qf[ks2], kf[nt]);
        }

        // ---- scale + causal mask
#pragma unroll
        for (int nt = 0; nt < 8; nt++) {
            s[nt][0] *= 0.125f; s[nt][1] *= 0.125f;
            s[nt][2] *= 0.125f; s[nt][3] *= 0.125f;
        }
        if (kt >= 2 * qt) {
            int relk = (kt - 2 * qt) * 64;
#pragma unroll
            for (int nt = 0; nt < 8; nt++) {
                int k0 = relk + nt * 8 + 2 * t4;
                if (k0 > row0)         s[nt][0] = -1e30f;
                if (k0 + 1 > row0)     s[nt][1] = -1e30f;
                if (k0 > row0 + 8)     s[nt][2] = -1e30f;
                if (k0 + 1 > row0 + 8) s[nt][3] = -1e30f;
            }
        }

        // ---- online softmax (warp-local rows); rounded P to smem
        float tm0 = -1e30f, tm1 = -1e30f;
#pragma unroll
        for (int nt = 0; nt < 8; nt++) {
            tm0 = fmaxf(tm0, fmaxf(s[nt][0], s[nt][1]));
            tm1 = fmaxf(tm1, fmaxf(s[nt][2], s[nt][3]));
        }
        tm0 = fmaxf(tm0, __shfl_xor_sync(0xffffffffu, tm0, 1));
        tm0 = fmaxf(tm0, __shfl_xor_sync(0xffffffffu, tm0, 2));
        tm1 = fmaxf(tm1, __shfl_xor_sync(0xffffffffu, tm1, 1));
        tm1 = fmaxf(tm1, __shfl_xor_sync(0xffffffffu, tm1, 2));
        float mn0 = fmaxf(m0, tm0), mn1 = fmaxf(m1, tm1);
        float al0 = __expf(m0 - mn0), al1 = __expf(m1 - mn1);
        float rs0 = 0.f, rs1 = 0.f;
#pragma unroll
        for (int nt = 0; nt < 8; nt++) {
            float p0 = rna_tf32(__expf(s[nt][0] - mn0));
            float p1 = rna_tf32(__expf(s[nt][1] - mn0));
            float p2 = rna_tf32(__expf(s[nt][2] - mn1));
            float p3 = rna_tf32(__expf(s[nt][3] - mn1));
            rs0 += p0 + p1; rs1 += p2 + p3;
            *(float2*)&Ps[row0 * QSTR + nt * 8 + 2 * t4]       = make_float2(p0, p1);
            *(float2*)&Ps[(row0 + 8) * QSTR + nt * 8 + 2 * t4] = make_float2(p2, p3);
        }
        rs0 += __shfl_xor_sync(0xffffffffu, rs0, 1);
        rs0 += __shfl_xor_sync(0xffffffffu, rs0, 2);
        rs1 += __shfl_xor_sync(0xffffffffu, rs1, 1);
        rs1 += __shfl_xor_sync(0xffffffffu, rs1, 2);
        l0 = l0 * al0 + rs0; l1 = l1 * al1 + rs1;
        m0 = mn0; m1 = mn1;
#pragma unroll
        for (int nt = 0; nt < 8; nt++) {
            accO[nt][0] *= al0; accO[nt][1] *= al0;
            accO[nt][2] *= al1; accO[nt][3] *= al1;
        }
        __syncwarp();   // P rows warp-private: warp sync suffices

        // ---- O += P @ V  (P A-frags via ldmatrix; V scalar LDS)
#pragma unroll
        for (int ks2 = 0; ks2 < 8; ks2++) {
            uint32_t pf[4];
            ldsm_x4(pf, ps_base + qp_off + ks2 * 32);
            int vr0 = (ks2 * 8 + t4) * VSTR + grp;
            int vr1 = (ks2 * 8 + t4 + 4) * VSTR + grp;
#pragma unroll
            for (int nt = 0; nt < 8; nt++) {
                uint32_t bf[2];
                bf[0] = Vu[vr0 + nt * 8];
                bf[1] = Vu[vr1 + nt * 8];
                mma_tf32(accO[nt], pf, bf);
            }
        }
    }

    // ---- normalize + write (tf32-rounded, feeds tf32 O-proj)
    float inv0 = 1.f / l0, inv1 = 1.f / l1;
    int sq0 = qt * 128 + row0;
    float* O0 = g_ao + ((size_t)b * SEQ + sq0) * DM + h * DH;
    float* O1 = g_ao + ((size_t)b * SEQ + sq0 + 8) * DM + h * DH;
#pragma unroll
    for (int nt = 0; nt < 8; nt++) {
        int c = nt * 8 + 2 * t4;
        *(float2*)&O0[c] = make_float2(rna_tf32(accO[nt][0] * inv0),
                                       rna_tf32(accO[nt][1] * inv0));
        *(float2*)&O1[c] = make_float2(rna_tf32(accO[nt][2] * inv1),
                                       rna_tf32(accO[nt][3] * inv1));
    }
}

// ---------------------------------------------------------------------------
extern "C" void kernel_launch(void* const* d_in, const int* in_sizes, int n_in,
                              void* d_out, int out_size)
{
    const float* x    = (const float*)d_in[0];
    const float* Wqkv = (const float*)d_in[1];
    const float* Wo   = (const float*)d_in[2];
    float* out = (float*)d_out;

    cudaFuncSetAttribute(flash_mma,
                         cudaFuncAttributeMaxDynamicSharedMemorySize, FM_SMEM);
    cudaFuncSetAttribute(gemm_mma<0>,
                         cudaFuncAttributeMaxDynamicSharedMemorySize, GEMM_SMEM);
    cudaFuncSetAttribute(gemm_mma<1>,
                         cudaFuncAttributeMaxDynamicSharedMemorySize, GEMM_SMEM);

    int n4x = BATCH * SEQ * DM / 4;
    int n4w = QKVN * DM / 4;
    int n4o = DM * DM / 4;
    float* gx;  cudaGetSymbolAddress((void**)&gx,  g_xr);
    float* gw;  cudaGetSymbolAddress((void**)&gw,  g_wr);
    float* gwo; cudaGetSymbolAddress((void**)&gwo, g_wor);

    // 1) tf32-round GEMM inputs
    round_tf32_kernel<<<(n4x + 255) / 256, 256>>>(x, gx, n4x);
    round_tf32_kernel<<<(n4w + 255) / 256, 256>>>(Wqkv, gw, n4w);
    round_tf32_kernel<<<(n4o + 255) / 256, 256>>>(Wo, gwo, n4o);

    // 2) QKV projection (tf32 mma.sync)
    gemm_mma<0><<<dim3(QKVN / 128, (BATCH * SEQ) / 128), 256, GEMM_SMEM>>>(
        gx, gw, nullptr, BATCH * SEQ, QKVN, DM);

    // 3) Causal flash attention (tf32 mma.sync)
    flash_mma<<<dim3(SEQ / 128, BATCH * NH), 256, FM_SMEM>>>();

    // 4) Output projection (tf32 mma.sync)
    gemm_mma<1><<<dim3(DM / 128, (BATCH * SEQ) / 128), 256, GEMM_SMEM>>>(
        nullptr, gwo, out, BATCH * SEQ, DM, DM);
}

// round 10
// speedup vs baseline: 1.1147x; 1.0876x over previous
#include <cuda_runtime.h>
#include <cstdint>

#define BATCH 4
#define SEQ   2048
#define NH    16
#define DH    64
#define DM    1024
#define QKVN  3072

// Scratch (device globals -- allocation-free per harness rules)
__device__ float g_q[(size_t)BATCH * NH * SEQ * DH];   // [b][h][s][dh] (tf32-rounded)
__device__ float g_k[(size_t)BATCH * NH * SEQ * DH];
__device__ float g_v[(size_t)BATCH * NH * SEQ * DH];
__device__ float g_ao[(size_t)BATCH * SEQ * DM];       // [b][s][d] attn out (tf32-rounded)
__device__ float g_xr[(size_t)BATCH * SEQ * DM];       // tf32-rounded x
__device__ float g_wr[(size_t)QKVN * DM];              // tf32-rounded W_qkv
__device__ float g_wor[(size_t)DM * DM];               // tf32-rounded W_o

// ---------------------------------------------------------------------------
// PTX helpers (portable: mma.sync + cp.async + ldmatrix, no 'a'-features)
// ---------------------------------------------------------------------------
__device__ __forceinline__ uint32_t smem_u32(const void* p) {
    uint32_t a;
    asm("{ .reg .u64 t; cvta.to.shared.u64 t, %1; cvt.u32.u64 %0, t; }" : "=r"(a) : "l"(p));
    return a;
}
__device__ __forceinline__ void cp_async16(uint32_t dst, const void* src) {
    asm volatile("cp.async.cg.shared.global [%0], [%1], 16;" :: "r"(dst), "l"(src) : "memory");
}
__device__ __forceinline__ void cp_commit() { asm volatile("cp.async.commit_group;" ::: "memory"); }
template <int N> __device__ __forceinline__ void cp_wait() {
    asm volatile("cp.async.wait_group %0;" :: "n"(N) : "memory");
}
__device__ __forceinline__ float rna_tf32(float x) {
    uint32_t u;
    asm("cvt.rna.tf32.f32 %0, %1;" : "=r"(u) : "f"(x));
    return __uint_as_float(u);
}
// D += A(16x8) * B(8x8), tf32 operands, fp32 accumulate
__device__ __forceinline__ void mma_tf32(float* d, const uint32_t* a, const uint32_t* b) {
    asm volatile(
        "mma.sync.aligned.m16n8k8.row.col.f32.tf32.tf32.f32 "
        "{%0,%1,%2,%3}, {%4,%5,%6,%7}, {%8,%9}, {%0,%1,%2,%3};"
        : "+f"(d[0]), "+f"(d[1]), "+f"(d[2]), "+f"(d[3])
        : "r"(a[0]), "r"(a[1]), "r"(a[2]), "r"(a[3]), "r"(b[0]), "r"(b[1]));
}
// 16x8 fp32 tile = four 8x8 b16 matrices; x4 yields the tf32 A fragment.
__device__ __forceinline__ void ldsm_x4(uint32_t* r, uint32_t addr) {
    asm volatile("ldmatrix.sync.aligned.m8n8.x4.shared.b16 {%0,%1,%2,%3}, [%4];"
        : "=r"(r[0]), "=r"(r[1]), "=r"(r[2]), "=r"(r[3]) : "r"(addr));
}
// 8x8 fp32 tile = two 8x8 b16 matrices; x2 yields the tf32 B fragment.
__device__ __forceinline__ void ldsm_x2(uint32_t* r, uint32_t addr) {
    asm volatile("ldmatrix.sync.aligned.m8n8.x2.shared.b16 {%0,%1}, [%2];"
        : "=r"(r[0]), "=r"(r[1]) : "r"(addr));
}

// ---------------------------------------------------------------------------
// Elementwise tf32 RNA round pass
// ---------------------------------------------------------------------------
__global__ void round_tf32_kernel(const float* __restrict__ src, float* __restrict__ dst, int n4)
{
    int i = blockIdx.x * blockDim.x + threadIdx.x;
    if (i < n4) {
        float4 v = ((const float4*)src)[i];
        v.x = rna_tf32(v.x); v.y = rna_tf32(v.y);
        v.z = rna_tf32(v.z); v.w = rna_tf32(v.w);
        ((float4*)dst)[i] = v;
    }
}

// ---------------------------------------------------------------------------
// TF32 mma.sync GEMM: C[M,N] = A[M,K] @ B[N,K]^T.  128x256 CTA tile, BK=32,
// 8 warps 2x4 -> 64x64 warp tile (FLOP/byte 16 vs 10.7: smem-bandwidth relief).
// Double-buffered cp.async; ldmatrix fragment loads.
// MODE 0: scatter C into g_q/g_k/g_v with rna-tf32 rounding.
// MODE 1: A = g_ao, write C row-major fp32 (final output).
// ---------------------------------------------------------------------------
#define TSTR    36
#define TILE_A  (128 * TSTR)            // floats
#define TILE_B  (256 * TSTR)
#define STAGE_F (TILE_A + TILE_B)
#define GEMM_SMEM (2 * STAGE_F * 4)     // 110592 B

template <int MODE>
__global__ __launch_bounds__(256) void gemm_mma(
    const float* __restrict__ A, const float* __restrict__ Bw,
    float* __restrict__ C, int M, int N, int K)
{
    extern __shared__ float smem[];
    uint32_t sbase = smem_u32(smem);

    const float* Ap = (MODE == 1) ? g_ao : A;

    int tid = threadIdx.x;
    int wid = tid >> 5, lane = tid & 31;
    int grp = lane >> 2, thr4 = lane & 3;
    int wm = wid >> 2, wn = wid & 3;          // warp tile 64x64: m=wm*64, n=wn*64
    int m0 = blockIdx.y << 7, n0 = blockIdx.x << 8;
    int nchunk = K >> 5;

    // ldmatrix per-lane byte offsets (validated in R7)
    uint32_t a_off = (uint32_t)(((wm * 64 + (lane & 7) + ((lane >> 3) & 1) * 8) * TSTR
                                + ((lane >> 4) * 4)) * 4);
    uint32_t b_off = (uint32_t)(((wn * 64 + (lane & 7)) * TSTR
                                + (((lane >> 3) & 1) * 4)) * 4);

    float acc[4][8][4];
#pragma unroll
    for (int mt = 0; mt < 4; mt++)
#pragma unroll
        for (int nt = 0; nt < 8; nt++)
#pragma unroll
            for (int e = 0; e < 4; e++) acc[mt][nt][e] = 0.f;

    auto load_chunk = [&](int chunk) {
        int buf = chunk & 1;
        uint32_t abase = sbase + (uint32_t)buf * STAGE_F * 4;
        uint32_t bbase = abase + TILE_A * 4;
        int k0 = chunk << 5;
#pragma unroll
        for (int q = 0; q < 4; q++) {          // A: 128 rows x 8 float4
            int idx = q * 256 + tid;
            int row = idx >> 3, c4 = idx & 7;
            cp_async16(abase + (uint32_t)(row * TSTR + c4 * 4) * 4,
                       Ap + (size_t)(m0 + row) * K + k0 + c4 * 4);
        }
#pragma unroll
        for (int q = 0; q < 8; q++) {          // B: 256 rows x 8 float4
            int idx = q * 256 + tid;
            int row = idx >> 3, c4 = idx & 7;
            cp_async16(bbase + (uint32_t)(row * TSTR + c4 * 4) * 4,
                       Bw + (size_t)(n0 + row) * K + k0 + c4 * 4);
        }
        cp_commit();
    };

    load_chunk(0);

    for (int i = 0; i < nchunk; i++) {
        if (i + 1 < nchunk) { load_chunk(i + 1); cp_wait<1>(); }
        else                { cp_wait<0>(); }
        __syncthreads();

        uint32_t abuf = sbase + (uint32_t)(i & 1) * STAGE_F * 4;
        uint32_t bbuf = abuf + TILE_A * 4;

#pragma unroll
        for (int ks = 0; ks < 4; ks++) {
            uint32_t afr[4][4], bfr[8][2];
#pragma unroll
            for (int mt = 0; mt < 4; mt++)
                ldsm_x4(afr[mt], abuf + a_off + mt * (16 * TSTR * 4) + ks * 32);
#pragma unroll
            for (int nt = 0; nt < 8; nt++)
                ldsm_x2(bfr[nt], bbuf + b_off + nt * (8 * TSTR * 4) + ks * 32);
#pragma unroll
            for (int mt = 0; mt < 4; mt++)
#pragma unroll
                for (int nt = 0; nt < 8; nt++)
                    mma_tf32(acc[mt][nt], afr[mt], bfr[nt]);
        }
        __syncthreads();
    }

#pragma unroll
    for (int mt = 0; mt < 4; mt++) {
#pragma unroll
        for (int nt = 0; nt < 8; nt++) {
            int m = m0 + wm * 64 + mt * 16 + grp;
            int n = n0 + wn * 64 + nt * 8 + 2 * thr4;
            if (MODE == 0) {
                float2 lo = make_float2(rna_tf32(acc[mt][nt][0]), rna_tf32(acc[mt][nt][1]));
                float2 hi = make_float2(rna_tf32(acc[mt][nt][2]), rna_tf32(acc[mt][nt][3]));
                int part = n >> 10;
                int d = n & 1023, h = d >> 6, dc = d & 63;
                float* dst = (part == 0) ? g_q : (part == 1) ? g_k : g_v;
                int b1 = m >> 11, s1 = m & 2047;
                *(float2*)(dst + ((((size_t)b1 * NH + h) * SEQ + s1) << 6) + dc) = lo;
                int s2 = (m + 8) & 2047;
                *(float2*)(dst + ((((size_t)b1 * NH + h) * SEQ + s2) << 6) + dc) = hi;
            } else {
                *(float2*)(C + (size_t)m * N + n) =
                    make_float2(acc[mt][nt][0], acc[mt][nt][1]);
                *(float2*)(C + (size_t)(m + 8) * N + n) =
                    make_float2(acc[mt][nt][2], acc[mt][nt][3]);
            }
        }
    }
}

// ---------------------------------------------------------------------------
// Tensor-core flash attention (tf32 mma.sync) -- proven R5 variant (866.9us
// run): Q-tile 128 x K-tile 64, 8 warps, warp-local softmax, single KV
// buffer, P through warp-private smem.
// ---------------------------------------------------------------------------
#define QSTR 68
#define VSTR 72
#define FM_SMEM ((128 * QSTR + 64 * QSTR + 64 * VSTR + 128 * QSTR) * 4)

__global__ __launch_bounds__(256, 2) void flash_mma()
{
    extern __shared__ float sm[];
    float* Qs = sm;                        // [128][68]
    float* Ks = Qs + 128 * QSTR;           // [64][68]
    float* Vs = Ks + 64 * QSTR;            // [64][72]
    float* Ps = Vs + 64 * VSTR;            // [128][68]
    uint32_t ks_base = smem_u32(Ks);
    uint32_t vs_base = smem_u32(Vs);

    int qt = blockIdx.x, bh = blockIdx.y;
    int b = bh >> 4, h = bh & 15;
    int tid = threadIdx.x, wid = tid >> 5, lane = tid & 31;
    int grp = lane >> 2, t4 = lane & 3;

    const float* Qg = g_q + ((size_t)bh * SEQ + (size_t)qt * 128) * DH;
    const float* Kg = g_k + (size_t)bh * SEQ * DH;
    const float* Vg = g_v + (size_t)bh * SEQ * DH;

    // Load Q tile: 128 rows x 64 cols = 2048 float4
#pragma unroll
    for (int u = 0; u < 8; u++) {
        int idx = u * 256 + tid;
        int r = idx >> 4, c4 = (idx & 15) << 2;
        *(float4*)&Qs[r * QSTR + c4] = *(const float4*)&Qg[r * DH + c4];
    }

    float accO[8][4];
#pragma unroll
    for (int nt = 0; nt < 8; nt++)
#pragma unroll
        for (int e = 0; e < 4; e++) accO[nt][e] = 0.f;
    float m0 = -1e30f, m1 = -1e30f, l0 = 0.f, l1 = 0.f;

    __syncthreads();

    int row0 = wid * 16 + grp;
    const uint32_t* Qu = (const uint32_t*)Qs;
    const uint32_t* Ku = (const uint32_t*)Ks;
    const uint32_t* Vu = (const uint32_t*)Vs;
    const uint32_t* Pu = (const uint32_t*)Ps;

    int nkt = 2 * qt + 2;
    for (int kt = 0; kt < nkt; kt++) {
#pragma unroll
        for (int u = 0; u < 4; u++) {
            int idx = u * 256 + tid;
            int r = idx >> 4, c4 = (idx & 15) << 2;
            cp_async16(ks_base + (uint32_t)(r * QSTR + c4) * 4,
                       Kg + ((size_t)kt * 64 + r) * DH + c4);
            cp_async16(vs_base + (uint32_t)(r * VSTR + c4) * 4,
                       Vg + ((size_t)kt * 64 + r) * DH + c4);
        }
        cp_commit();
        cp_wait<0>();
        __syncthreads();

        // ---- S = Q @ K^T
        float s[8][4];
#pragma unroll
        for (int nt = 0; nt < 8; nt++)
#pragma unroll
            for (int e = 0; e < 4; e++) s[nt][e] = 0.f;

#pragma unroll
        for (int ks2 = 0; ks2 < 8; ks2++) {
            int ca = ks2 * 8 + t4;
            uint32_t a[4];
            a[0] = Qu[row0 * QSTR + ca];
            a[1] = Qu[(row0 + 8) * QSTR + ca];
            a[2] = Qu[row0 * QSTR + ca + 4];
            a[3] = Qu[(row0 + 8) * QSTR + ca + 4];
#pragma unroll
            for (int nt = 0; nt < 8; nt++) {
                uint32_t bf[2];
                bf[0] = Ku[(nt * 8 + grp) * QSTR + ca];
                bf[1] = Ku[(nt * 8 + grp) * QSTR + ca + 4];
                mma_tf32(s[nt], a, bf);
            }
        }

        // ---- scale + causal mask
#pragma unroll
        for (int nt = 0; nt < 8; nt++) {
            s[nt][0] *= 0.125f; s[nt][1] *= 0.125f;
            s[nt][2] *= 0.125f; s[nt][3] *= 0.125f;
        }
        if (kt >= 2 * qt) {
            int relk = (kt - 2 * qt) * 64;
#pragma unroll
            for (int nt = 0; nt < 8; nt++) {
                int k0 = relk + nt * 8 + 2 * t4;
                if (k0 > row0)         s[nt][0] = -1e30f;
                if (k0 + 1 > row0)     s[nt][1] = -1e30f;
                if (k0 > row0 + 8)     s[nt][2] = -1e30f;
                if (k0 + 1 > row0 + 8) s[nt][3] = -1e30f;
            }
        }

        // ---- online softmax (warp-local rows); rounded P to smem
        float tm0 = -1e30f, tm1 = -1e30f;
#pragma unroll
        for (int nt = 0; nt < 8; nt++) {
            tm0 = fmaxf(tm0, fmaxf(s[nt][0], s[nt][1]));
            tm1 = fmaxf(tm1, fmaxf(s[nt][2], s[nt][3]));
        }
        tm0 = fmaxf(tm0, __shfl_xor_sync(0xffffffffu, tm0, 1));
        tm0 = fmaxf(tm0, __shfl_xor_sync(0xffffffffu, tm0, 2));
        tm1 = fmaxf(tm1, __shfl_xor_sync(0xffffffffu, tm1, 1));
        tm1 = fmaxf(tm1, __shfl_xor_sync(0xffffffffu, tm1, 2));
        float mn0 = fmaxf(m0, tm0), mn1 = fmaxf(m1, tm1);
        float al0 = __expf(m0 - mn0), al1 = __expf(m1 - mn1);
        float rs0 = 0.f, rs1 = 0.f;
#pragma unroll
        for (int nt = 0; nt < 8; nt++) {
            float p0 = rna_tf32(__expf(s[nt][0] - mn0));
            float p1 = rna_tf32(__expf(s[nt][1] - mn0));
            float p2 = rna_tf32(__expf(s[nt][2] - mn1));
            float p3 = rna_tf32(__expf(s[nt][3] - mn1));
            rs0 += p0 + p1; rs1 += p2 + p3;
            *(float2*)&Ps[row0 * QSTR + nt * 8 + 2 * t4]       = make_float2(p0, p1);
            *(float2*)&Ps[(row0 + 8) * QSTR + nt * 8 + 2 * t4] = make_float2(p2, p3);
        }
        rs0 += __shfl_xor_sync(0xffffffffu, rs0, 1);
        rs0 += __shfl_xor_sync(0xffffffffu, rs0, 2);
        rs1 += __shfl_xor_sync(0xffffffffu, rs1, 1);
        rs1 += __shfl_xor_sync(0xffffffffu, rs1, 2);
        l0 = l0 * al0 + rs0; l1 = l1 * al1 + rs1;
        m0 = mn0; m1 = mn1;
#pragma unroll
        for (int nt = 0; nt < 8; nt++) {
            accO[nt][0] *= al0; accO[nt][1] *= al0;
            accO[nt][2] *= al1; accO[nt][3] *= al1;
        }
        __syncwarp();   // P rows warp-private

        // ---- O += P @ V
#pragma unroll
        for (int ks2 = 0; ks2 < 8; ks2++) {
            int ca = ks2 * 8 + t4;
            uint32_t a[4];
            a[0] = Pu[row0 * QSTR + ca];
            a[1] = Pu[(row0 + 8) * QSTR + ca];
            a[2] = Pu[row0 * QSTR + ca + 4];
            a[3] = Pu[(row0 + 8) * QSTR + ca + 4];
            int vr0 = (ks2 * 8 + t4) * VSTR + grp;
            int vr1 = (ks2 * 8 + t4 + 4) * VSTR + grp;
#pragma unroll
            for (int nt = 0; nt < 8; nt++) {
                uint32_t bf[2];
                bf[0] = Vu[vr0 + nt * 8];
                bf[1] = Vu[vr1 + nt * 8];
                mma_tf32(accO[nt], a, bf);
            }
        }
        __syncthreads();   // protect Ks/Vs before next tile's cp.async
    }

    // ---- normalize + write (tf32-rounded, feeds tf32 O-proj)
    float inv0 = 1.f / l0, inv1 = 1.f / l1;
    int sq0 = qt * 128 + row0;
    float* O0 = g_ao + ((size_t)b * SEQ + sq0) * DM + h * DH;
    float* O1 = g_ao + ((size_t)b * SEQ + sq0 + 8) * DM + h * DH;
#pragma unroll
    for (int nt = 0; nt < 8; nt++) {
        int c = nt * 8 + 2 * t4;
        *(float2*)&O0[c] = make_float2(rna_tf32(accO[nt][0] * inv0),
                                       rna_tf32(accO[nt][1] * inv0));
        *(float2*)&O1[c] = make_float2(rna_tf32(accO[nt][2] * inv1),
                                       rna_tf32(accO[nt][3] * inv1));
    }
}

// ---------------------------------------------------------------------------
extern "C" void kernel_launch(void* const* d_in, const int* in_sizes, int n_in,
                              void* d_out, int out_size)
{
    const float* x    = (const float*)d_in[0];
    const float* Wqkv = (const float*)d_in[1];
    const float* Wo   = (const float*)d_in[2];
    float* out = (float*)d_out;

    cudaFuncSetAttribute(flash_mma,
                         cudaFuncAttributeMaxDynamicSharedMemorySize, FM_SMEM);
    cudaFuncSetAttribute(gemm_mma<0>,
                         cudaFuncAttributeMaxDynamicSharedMemorySize, GEMM_SMEM);
    cudaFuncSetAttribute(gemm_mma<1>,
                         cudaFuncAttributeMaxDynamicSharedMemorySize, GEMM_SMEM);

    int n4x = BATCH * SEQ * DM / 4;
    int n4w = QKVN * DM / 4;
    int n4o = DM * DM / 4;
    float* gx;  cudaGetSymbolAddress((void**)&gx,  g_xr);
    float* gw;  cudaGetSymbolAddress((void**)&gw,  g_wr);
    float* gwo; cudaGetSymbolAddress((void**)&gwo, g_wor);

    // 1) tf32-round GEMM inputs
    round_tf32_kernel<<<(n4x + 255) / 256, 256>>>(x, gx, n4x);
    round_tf32_kernel<<<(n4w + 255) / 256, 256>>>(Wqkv, gw, n4w);
    round_tf32_kernel<<<(n4o + 255) / 256, 256>>>(Wo, gwo, n4o);

    // 2) QKV projection (tf32 mma.sync, 128x256 CTA tile)
    gemm_mma<0><<<dim3(QKVN / 256, (BATCH * SEQ) / 128), 256, GEMM_SMEM>>>(
        gx, gw, nullptr, BATCH * SEQ, QKVN, DM);

    // 3) Causal flash attention (tf32 mma.sync)
    flash_mma<<<dim3(SEQ / 128, BATCH * NH), 256, FM_SMEM>>>();

    // 4) Output projection (tf32 mma.sync, 128x256 CTA tile)
    gemm_mma<1><<<dim3(DM / 256, (BATCH * SEQ) / 128), 256, GEMM_SMEM>>>(
        nullptr, gwo, out, BATCH * SEQ, DM, DM);
}

// round 14
// speedup vs baseline: 1.4309x; 1.2837x over previous
#include <cuda_runtime.h>
#include <cuda_fp16.h>
#include <cstdint>

#define BATCH 4
#define SEQ   2048
#define NH    16
#define DH    64
#define DM    1024
#define QKVN  3072

// Scratch: q/k/v fp32 (tf32 flash reads), g_ao half (fp16 O-proj reads)
__device__ float  g_q[(size_t)BATCH * NH * SEQ * DH];   // [b][h][s][dh] tf32-rounded
__device__ float  g_k[(size_t)BATCH * NH * SEQ * DH];
__device__ float  g_v[(size_t)BATCH * NH * SEQ * DH];
__device__ __half g_ao[(size_t)BATCH * SEQ * DM];       // attn out (half)
__device__ __half g_xh[(size_t)BATCH * SEQ * DM];       // half-rounded x
__device__ __half g_wh[(size_t)QKVN * DM];              // half-rounded W_qkv
__device__ __half g_woh[(size_t)DM * DM];               // half-rounded W_o

// ---------------------------------------------------------------------------
// PTX helpers
// ---------------------------------------------------------------------------
__device__ __forceinline__ uint32_t smem_u32(const void* p) {
    uint32_t a;
    asm("{ .reg .u64 t; cvta.to.shared.u64 t, %1; cvt.u32.u64 %0, t; }" : "=r"(a) : "l"(p));
    return a;
}
__device__ __forceinline__ void cp_async16(uint32_t dst, const void* src) {
    asm volatile("cp.async.cg.shared.global [%0], [%1], 16;" :: "r"(dst), "l"(src) : "memory");
}
__device__ __forceinline__ void cp_commit() { asm volatile("cp.async.commit_group;" ::: "memory"); }
template <int N> __device__ __forceinline__ void cp_wait() {
    asm volatile("cp.async.wait_group %0;" :: "n"(N) : "memory");
}
__device__ __forceinline__ float rna_tf32(float x) {
    uint32_t u;
    asm("cvt.rna.tf32.f32 %0, %1;" : "=r"(u) : "f"(x));
    return __uint_as_float(u);
}
// fp16 m16n8k16: D += A*B, fp32 accumulate
__device__ __forceinline__ void mma_f16(float* d, const uint32_t* a, const uint32_t* b) {
    asm volatile(
        "mma.sync.aligned.m16n8k16.row.col.f32.f16.f16.f32 "
        "{%0,%1,%2,%3}, {%4,%5,%6,%7}, {%8,%9}, {%0,%1,%2,%3};"
        : "+f"(d[0]), "+f"(d[1]), "+f"(d[2]), "+f"(d[3])
        : "r"(a[0]), "r"(a[1]), "r"(a[2]), "r"(a[3]), "r"(b[0]), "r"(b[1]));
}
// tf32 m16n8k8 (proven flash path)
__device__ __forceinline__ void mma_tf32(float* d, const uint32_t* a, const uint32_t* b) {
    asm volatile(
        "mma.sync.aligned.m16n8k8.row.col.f32.tf32.tf32.f32 "
        "{%0,%1,%2,%3}, {%4,%5,%6,%7}, {%8,%9}, {%0,%1,%2,%3};"
        : "+f"(d[0]), "+f"(d[1]), "+f"(d[2]), "+f"(d[3])
        : "r"(a[0]), "r"(a[1]), "r"(a[2]), "r"(a[3]), "r"(b[0]), "r"(b[1]));
}
__device__ __forceinline__ void ldsm_x4(uint32_t* r, uint32_t addr) {
    asm volatile("ldmatrix.sync.aligned.m8n8.x4.shared.b16 {%0,%1,%2,%3}, [%4];"
        : "=r"(r[0]), "=r"(r[1]), "=r"(r[2]), "=r"(r[3]) : "r"(addr));
}
__device__ __forceinline__ void ldsm_x2(uint32_t* r, uint32_t addr) {
    asm volatile("ldmatrix.sync.aligned.m8n8.x2.shared.b16 {%0,%1}, [%2];"
        : "=r"(r[0]), "=r"(r[1]) : "r"(addr));
}

// ---------------------------------------------------------------------------
// float -> half RN conversion pass
// ---------------------------------------------------------------------------
__global__ void round_h_kernel(const float* __restrict__ src, __half* __restrict__ dst, int n4)
{
    int i = blockIdx.x * blockDim.x + threadIdx.x;
    if (i < n4) {
        float4 v = ((const float4*)src)[i];
        ((__half2*)dst)[2 * i]     = __floats2half2_rn(v.x, v.y);
        ((__half2*)dst)[2 * i + 1] = __floats2half2_rn(v.z, v.w);
    }
}

// ---------------------------------------------------------------------------
// FP16 mma.sync GEMM: C[M,N] = A[M,K] @ B[N,K]^T.  128x256 CTA tile, BK=32
// halves, 8 warps 2x4 -> 64x64 warp tile, m16n8k16.
// MODE 0: scatter fp32 (rna-tf32) into g_q/g_k/g_v.  MODE 1: A=g_ao, C fp32.
// ---------------------------------------------------------------------------
#define TSH     40
#define TILE_AH (128 * TSH)
#define TILE_BH (256 * TSH)
#define STAGE_H (TILE_AH + TILE_BH)
#define GEMM_SMEM (2 * STAGE_H * 2)

template <int MODE>
__global__ __launch_bounds__(256) void gemm_mma(
    const __half* __restrict__ A, const __half* __restrict__ Bw,
    float* __restrict__ C, int M, int N, int K)
{
    extern __shared__ __half smh[];
    uint32_t sbase = smem_u32(smh);

    const __half* Ap = (MODE == 1) ? g_ao : A;

    int tid = threadIdx.x;
    int wid = tid >> 5, lane = tid & 31;
    int grp = lane >> 2, thr4 = lane & 3;
    int wm = wid >> 2, wn = wid & 3;
    int m0 = blockIdx.y << 7, n0 = blockIdx.x << 8;
    int nchunk = K >> 5;

    uint32_t a_off = (uint32_t)((wm * 64 + (lane & 7) + ((lane >> 3) & 1) * 8) * (TSH * 2)
                               + ((lane >> 4) & 1) * 16);
    uint32_t b_off = (uint32_t)((wn * 64 + (lane & 7)) * (TSH * 2)
                               + ((lane >> 3) & 1) * 16);

    float acc[4][8][4];
#pragma unroll
    for (int mt = 0; mt < 4; mt++)
#pragma unroll
        for (int nt = 0; nt < 8; nt++)
#pragma unroll
            for (int e = 0; e < 4; e++) acc[mt][nt][e] = 0.f;

    auto load_chunk = [&](int chunk) {
        int buf = chunk & 1;
        uint32_t abase = sbase + (uint32_t)buf * STAGE_H * 2;
        uint32_t bbase = abase + TILE_AH * 2;
        int k0 = chunk << 5;
#pragma unroll
        for (int q = 0; q < 2; q++) {
            int idx = q * 256 + tid;
            int row = idx >> 2, c16 = idx & 3;
            cp_async16(abase + (uint32_t)(row * (TSH * 2) + c16 * 16),
                       Ap + (size_t)(m0 + row) * K + k0 + c16 * 8);
        }
#pragma unroll
        for (int q = 0; q < 4; q++) {
            int idx = q * 256 + tid;
            int row = idx >> 2, c16 = idx & 3;
            cp_async16(bbase + (uint32_t)(row * (TSH * 2) + c16 * 16),
                       Bw + (size_t)(n0 + row) * K + k0 + c16 * 8);
        }
        cp_commit();
    };

    load_chunk(0);

    for (int i = 0; i < nchunk; i++) {
        if (i + 1 < nchunk) { load_chunk(i + 1); cp_wait<1>(); }
        else                { cp_wait<0>(); }
        __syncthreads();

        uint32_t abuf = sbase + (uint32_t)(i & 1) * STAGE_H * 2;
        uint32_t bbuf = abuf + TILE_AH * 2;

#pragma unroll
        for (int ks = 0; ks < 2; ks++) {
            uint32_t afr[4][4], bfr[8][2];
#pragma unroll
            for (int mt = 0; mt < 4; mt++)
                ldsm_x4(afr[mt], abuf + a_off + mt * (16 * TSH * 2) + ks * 32);
#pragma unroll
            for (int nt = 0; nt < 8; nt++)
                ldsm_x2(bfr[nt], bbuf + b_off + nt * (8 * TSH * 2) + ks * 32);
#pragma unroll
            for (int mt = 0; mt < 4; mt++)
#pragma unroll
                for (int nt = 0; nt < 8; nt++)
                    mma_f16(acc[mt][nt], afr[mt], bfr[nt]);
        }
        __syncthreads();
    }

#pragma unroll
    for (int mt = 0; mt < 4; mt++) {
#pragma unroll
        for (int nt = 0; nt < 8; nt++) {
            int m = m0 + wm * 64 + mt * 16 + grp;
            int n = n0 + wn * 64 + nt * 8 + 2 * thr4;
            if (MODE == 0) {
                float2 lo = make_float2(rna_tf32(acc[mt][nt][0]), rna_tf32(acc[mt][nt][1]));
                float2 hi = make_float2(rna_tf32(acc[mt][nt][2]), rna_tf32(acc[mt][nt][3]));
                int part = n >> 10;
                int d = n & 1023, h = d >> 6, dc = d & 63;
                float* dst = (part == 0) ? g_q : (part == 1) ? g_k : g_v;
                int b1 = m >> 11, s1 = m & 2047;
                *(float2*)(dst + ((((size_t)b1 * NH + h) * SEQ + s1) << 6) + dc) = lo;
                int s2 = (m + 8) & 2047;
                *(float2*)(dst + ((((size_t)b1 * NH + h) * SEQ + s2) << 6) + dc) = hi;
            } else {
                *(float2*)(C + (size_t)m * N + n) =
                    make_float2(acc[mt][nt][0], acc[mt][nt][1]);
                *(float2*)(C + (size_t)(m + 8) * N + n) =
                    make_float2(acc[mt][nt][2], acc[mt][nt][3]);
            }
        }
    }
}

// ---------------------------------------------------------------------------
// Tensor-core flash attention (tf32 mma.sync) -- PROVEN variant from the
// 841.8us run, verbatim except the final store converts O to __half.
// ---------------------------------------------------------------------------
#define QSTR 68
#define VSTR 72
#define FM_SMEM ((128 * QSTR + 64 * QSTR + 64 * VSTR + 128 * QSTR) * 4)

__global__ __launch_bounds__(256, 2) void flash_mma()
{
    extern __shared__ float sm[];
    float* Qs = sm;                        // [128][68]
    float* Ks = Qs + 128 * QSTR;           // [64][68]
    float* Vs = Ks + 64 * QSTR;            // [64][72]
    float* Ps = Vs + 64 * VSTR;            // [128][68]
    uint32_t ks_base = smem_u32(Ks);
    uint32_t vs_base = smem_u32(Vs);

    int qt = blockIdx.x, bh = blockIdx.y;
    int b = bh >> 4, h = bh & 15;
    int tid = threadIdx.x, wid = tid >> 5, lane = tid & 31;
    int grp = lane >> 2, t4 = lane & 3;

    const float* Qg = g_q + ((size_t)bh * SEQ + (size_t)qt * 128) * DH;
    const float* Kg = g_k + (size_t)bh * SEQ * DH;
    const float* Vg = g_v + (size_t)bh * SEQ * DH;

#pragma unroll
    for (int u = 0; u < 8; u++) {
        int idx = u * 256 + tid;
        int r = idx >> 4, c4 = (idx & 15) << 2;
        *(float4*)&Qs[r * QSTR + c4] = *(const float4*)&Qg[r * DH + c4];
    }

    float accO[8][4];
#pragma unroll
    for (int nt = 0; nt < 8; nt++)
#pragma unroll
        for (int e = 0; e < 4; e++) accO[nt][e] = 0.f;
    float m0 = -1e30f, m1 = -1e30f, l0 = 0.f, l1 = 0.f;

    __syncthreads();

    int row0 = wid * 16 + grp;
    const uint32_t* Qu = (const uint32_t*)Qs;
    const uint32_t* Ku = (const uint32_t*)Ks;
    const uint32_t* Vu = (const uint32_t*)Vs;
    const uint32_t* Pu = (const uint32_t*)Ps;

    int nkt = 2 * qt + 2;
    for (int kt = 0; kt < nkt; kt++) {
#pragma unroll
        for (int u = 0; u < 4; u++) {
            int idx = u * 256 + tid;
            int r = idx >> 4, c4 = (idx & 15) << 2;
            cp_async16(ks_base + (uint32_t)(r * QSTR + c4) * 4,
                       Kg + ((size_t)kt * 64 + r) * DH + c4);
            cp_async16(vs_base + (uint32_t)(r * VSTR + c4) * 4,
                       Vg + ((size_t)kt * 64 + r) * DH + c4);
        }
        cp_commit();
        cp_wait<0>();
        __syncthreads();

        float s[8][4];
#pragma unroll
        for (int nt = 0; nt < 8; nt++)
#pragma unroll
            for (int e = 0; e < 4; e++) s[nt][e] = 0.f;

#pragma unroll
        for (int ks2 = 0; ks2 < 8; ks2++) {
            int ca = ks2 * 8 + t4;
            uint32_t a[4];
            a[0] = Qu[row0 * QSTR + ca];
            a[1] = Qu[(row0 + 8) * QSTR + ca];
            a[2] = Qu[row0 * QSTR + ca + 4];
            a[3] = Qu[(row0 + 8) * QSTR + ca + 4];
#pragma unroll
            for (int nt = 0; nt < 8; nt++) {
                uint32_t bf[2];
                bf[0] = Ku[(nt * 8 + grp) * QSTR + ca];
                bf[1] = Ku[(nt * 8 + grp) * QSTR + ca + 4];
                mma_tf32(s[nt], a, bf);
            }
        }

#pragma unroll
        for (int nt = 0; nt < 8; nt++) {
            s[nt][0] *= 0.125f; s[nt][1] *= 0.125f;
            s[nt][2] *= 0.125f; s[nt][3] *= 0.125f;
        }
        if (kt >= 2 * qt) {
            int relk = (kt - 2 * qt) * 64;
#pragma unroll
            for (int nt = 0; nt < 8; nt++) {
                int k0 = relk + nt * 8 + 2 * t4;
                if (k0 > row0)         s[nt][0] = -1e30f;
                if (k0 + 1 > row0)     s[nt][1] = -1e30f;
                if (k0 > row0 + 8)     s[nt][2] = -1e30f;
                if (k0 + 1 > row0 + 8) s[nt][3] = -1e30f;
            }
        }

        float tm0 = -1e30f, tm1 = -1e30f;
#pragma unroll
        for (int nt = 0; nt < 8; nt++) {
            tm0 = fmaxf(tm0, fmaxf(s[nt][0], s[nt][1]));
            tm1 = fmaxf(tm1, fmaxf(s[nt][2], s[nt][3]));
        }
        tm0 = fmaxf(tm0, __shfl_xor_sync(0xffffffffu, tm0, 1));
        tm0 = fmaxf(tm0, __shfl_xor_sync(0xffffffffu, tm0, 2));
        tm1 = fmaxf(tm1, __shfl_xor_sync(0xffffffffu, tm1, 1));
        tm1 = fmaxf(tm1, __shfl_xor_sync(0xffffffffu, tm1, 2));
        float mn0 = fmaxf(m0, tm0), mn1 = fmaxf(m1, tm1);
        float al0 = __expf(m0 - mn0), al1 = __expf(m1 - mn1);
        float rs0 = 0.f, rs1 = 0.f;
#pragma unroll
        for (int nt = 0; nt < 8; nt++) {
            float p0 = rna_tf32(__expf(s[nt][0] - mn0));
            float p1 = rna_tf32(__expf(s[nt][1] - mn0));
            float p2 = rna_tf32(__expf(s[nt][2] - mn1));
            float p3 = rna_tf32(__expf(s[nt][3] - mn1));
            rs0 += p0 + p1; rs1 += p2 + p3;
            *(float2*)&Ps[row0 * QSTR + nt * 8 + 2 * t4]       = make_float2(p0, p1);
            *(float2*)&Ps[(row0 + 8) * QSTR + nt * 8 + 2 * t4] = make_float2(p2, p3);
        }
        rs0 += __shfl_xor_sync(0xffffffffu, rs0, 1);
        rs0 += __shfl_xor_sync(0xffffffffu, rs0, 2);
        rs1 += __shfl_xor_sync(0xffffffffu, rs1, 1);
        rs1 += __shfl_xor_sync(0xffffffffu, rs1, 2);
        l0 = l0 * al0 + rs0; l1 = l1 * al1 + rs1;
        m0 = mn0; m1 = mn1;
#pragma unroll
        for (int nt = 0; nt < 8; nt++) {
            accO[nt][0] *= al0; accO[nt][1] *= al0;
            accO[nt][2] *= al1; accO[nt][3] *= al1;
        }
        __syncwarp();

#pragma unroll
        for (int ks2 = 0; ks2 < 8; ks2++) {
            int ca = ks2 * 8 + t4;
            uint32_t a[4];
            a[0] = Pu[row0 * QSTR + ca];
            a[1] = Pu[(row0 + 8) * QSTR + ca];
            a[2] = Pu[row0 * QSTR + ca + 4];
            a[3] = Pu[(row0 + 8) * QSTR + ca + 4];
            int vr0 = (ks2 * 8 + t4) * VSTR + grp;
            int vr1 = (ks2 * 8 + t4 + 4) * VSTR + grp;
#pragma unroll
            for (int nt = 0; nt < 8; nt++) {
                uint32_t bf[2];
                bf[0] = Vu[vr0 + nt * 8];
                bf[1] = Vu[vr1 + nt * 8];
                mma_tf32(accO[nt], a, bf);
            }
        }
        __syncthreads();
    }

    // normalize + write O as half (feeds fp16 O-proj)
    float inv0 = 1.f / l0, inv1 = 1.f / l1;
    int sq0 = qt * 128 + row0;
    __half* O0 = g_ao + ((size_t)b * SEQ + sq0) * DM + h * DH;
    __half* O1 = g_ao + ((size_t)b * SEQ + sq0 + 8) * DM + h * DH;
#pragma unroll
    for (int nt = 0; nt < 8; nt++) {
        int c = nt * 8 + 2 * t4;
        *(__half2*)&O0[c] = __floats2half2_rn(accO[nt][0] * inv0, accO[nt][1] * inv0);
        *(__half2*)&O1[c] = __floats2half2_rn(accO[nt][2] * inv1, accO[nt][3] * inv1);
    }
}

// ---------------------------------------------------------------------------
extern "C" void kernel_launch(void* const* d_in, const int* in_sizes, int n_in,
                              void* d_out, int out_size)
{
    const float* x    = (const float*)d_in[0];
    const float* Wqkv = (const float*)d_in[1];
    const float* Wo   = (const float*)d_in[2];
    float* out = (float*)d_out;

    cudaFuncSetAttribute(flash_mma,
                         cudaFuncAttributeMaxDynamicSharedMemorySize, FM_SMEM);
    cudaFuncSetAttribute(gemm_mma<0>,
                         cudaFuncAttributeMaxDynamicSharedMemorySize, GEMM_SMEM);
    cudaFuncSetAttribute(gemm_mma<1>,
                         cudaFuncAttributeMaxDynamicSharedMemorySize, GEMM_SMEM);

    int n4x = BATCH * SEQ * DM / 4;
    int n4w = QKVN * DM / 4;
    int n4o = DM * DM / 4;
    __half* gx;  cudaGetSymbolAddress((void**)&gx,  g_xh);
    __half* gw;  cudaGetSymbolAddress((void**)&gw,  g_wh);
    __half* gwo; cudaGetSymbolAddress((void**)&gwo, g_woh);

    // 1) fp16-round GEMM inputs
    round_h_kernel<<<(n4x + 255) / 256, 256>>>(x, gx, n4x);
    round_h_kernel<<<(n4w + 255) / 256, 256>>>(Wqkv, gw, n4w);
    round_h_kernel<<<(n4o + 255) / 256, 256>>>(Wo, gwo, n4o);

    // 2) QKV projection (fp16 m16n8k16) -> fp32 q/k/v
    gemm_mma<0><<<dim3(QKVN / 256, (BATCH * SEQ) / 128), 256, GEMM_SMEM>>>(
        gx, gw, nullptr, BATCH * SEQ, QKVN, DM);

    // 3) Causal flash attention (tf32, proven) -> half g_ao
    flash_mma<<<dim3(SEQ / 128, BATCH * NH), 256, FM_SMEM>>>();

    // 4) Output projection (fp16 m16n8k16)
    gemm_mma<1><<<dim3(DM / 256, (BATCH * SEQ) / 128), 256, GEMM_SMEM>>>(
        nullptr, gwo, out, BATCH * SEQ, DM, DM);
}